// round 16
// baseline (speedup 1.0000x reference)
#include <cuda_runtime.h>
#include <math.h>
#include <stdint.h>

#define NROWS   262144
#define NCTA    2048
#define TILE_R  16                      // rows per pipeline stage (8 KB)
#define STAGES  4
#define NT      8                       // tiles per CTA

__device__ __forceinline__ void cpa16(uint32_t dst, const float4* src) {
    asm volatile("cp.async.cg.shared.global [%0], [%1], 16;"
                 :: "r"(dst), "l"(src));
}
__device__ __forceinline__ void cpa_commit() {
    asm volatile("cp.async.commit_group;");
}
__device__ __forceinline__ void cpa_wait3() {
    asm volatile("cp.async.wait_group 3;");
}

__global__ void __launch_bounds__(128, 5)
bdla_main(const float4* __restrict__ x, float4* __restrict__ y,
          const float* __restrict__ Wd, const float* __restrict__ s,
          const float* __restrict__ U, const float* __restrict__ V) {
    __shared__ float4 sx[STAGES][TILE_R * 32];        // 4 x 8 KB
    __shared__ __align__(16) float ssm[2][8][4];      // [pass][row][warp]

    const int tid  = threadIdx.x;
    const int lane = tid & 31;
    const int wid  = tid >> 5;          // 0..3
    const int q    = lane & 3;          // quad within block
    const int rl   = lane >> 2;         // row within 8-row pass
    const unsigned ctaRow0 = blockIdx.x * (TILE_R * NT);

    const float4* gsrc0 = x + (size_t)ctaRow0 * 32;
    const uint32_t sbase = (uint32_t)__cvta_generic_to_shared(&sx[0][0]);

    // Prologue: prefetch tiles 0..2 (common to both specializations).
    #pragma unroll
    for (int t = 0; t < STAGES - 1; ++t) {
        const uint32_t dst0 = sbase + (uint32_t)(t * TILE_R * 512);
        const float4* src0 = gsrc0 + t * TILE_R * 32;
        #pragma unroll
        for (int i = 0; i < 4; ++i)
            cpa16(dst0 + (tid + 128 * i) * 16u, src0 + tid + 128 * i);
        cpa_commit();
    }

    if (wid < 3) {
        // ───── Dense block 3*wid + diagonal block 3*wid+1 ─────
        // wt[o*4+dq] = W[wid][4q+o][4dq..4dq+3]  (row-major rows -> dot form)
        float4 wt[16];
        #pragma unroll
        for (int o = 0; o < 4; ++o) {
            const float4* rw = (const float4*)&Wd[wid * 256 + (4 * q + o) * 16];
            #pragma unroll
            for (int dq = 0; dq < 4; ++dq) wt[o * 4 + dq] = rw[dq];
        }
        const float4 sv = *(const float4*)&s[wid * 16 + 4 * q];
        const int pD = 12 * wid + q;          // dense out quad idx in row
        const int pG = (3 * wid + 1) * 4 + q; // diag out quad idx

        int stage = 0, pstage = STAGES - 1;
        #pragma unroll 1
        for (int t = 0; t < NT; ++t) {
            const int tp = t + STAGES - 1;
            if (tp < NT) {
                const uint32_t dst0 = sbase + (uint32_t)(pstage * TILE_R * 512);
                const float4* src0 = gsrc0 + tp * TILE_R * 32;
                #pragma unroll
                for (int i = 0; i < 4; ++i)
                    cpa16(dst0 + (tid + 128 * i) * 16u, src0 + tid + 128 * i);
            }
            cpa_commit();
            cpa_wait3();
            __syncthreads();                       // tile t visible; stage safe

            const float4* tile = &sx[stage][0];
            #pragma unroll
            for (int pass = 0; pass < 2; ++pass) {
                const int row = pass * 8 + rl;
                const float4* rowp = tile + row * 32;

                float d0 = 0.f, d1 = 0.f, d2 = 0.f, d3 = 0.f;
                #pragma unroll
                for (int sb = 0; sb < 4; ++sb) {
                    const float4 a = rowp[12 * wid + sb];
                    const float4 w0 = wt[0 + sb], w1 = wt[4 + sb];
                    const float4 w2 = wt[8 + sb], w3 = wt[12 + sb];
                    d0 = fmaf(a.x, w0.x, d0); d0 = fmaf(a.y, w0.y, d0);
                    d0 = fmaf(a.z, w0.z, d0); d0 = fmaf(a.w, w0.w, d0);
                    d1 = fmaf(a.x, w1.x, d1); d1 = fmaf(a.y, w1.y, d1);
                    d1 = fmaf(a.z, w1.z, d1); d1 = fmaf(a.w, w1.w, d1);
                    d2 = fmaf(a.x, w2.x, d2); d2 = fmaf(a.y, w2.y, d2);
                    d2 = fmaf(a.z, w2.z, d2); d2 = fmaf(a.w, w2.w, d2);
                    d3 = fmaf(a.x, w3.x, d3); d3 = fmaf(a.y, w3.y, d3);
                    d3 = fmaf(a.z, w3.z, d3); d3 = fmaf(a.w, w3.w, d3);
                }
                const float4 ag = rowp[pG];
                const float g0 = ag.x * sv.x, g1 = ag.y * sv.y;
                const float g2 = ag.z * sv.z, g3 = ag.w * sv.w;

                float ss = d0 * d0;
                ss = fmaf(d1, d1, ss); ss = fmaf(d2, d2, ss);
                ss = fmaf(d3, d3, ss);
                ss = fmaf(g0, g0, ss); ss = fmaf(g1, g1, ss);
                ss = fmaf(g2, g2, ss); ss = fmaf(g3, g3, ss);
                ss += __shfl_xor_sync(0xffffffffu, ss, 1);
                ss += __shfl_xor_sync(0xffffffffu, ss, 2);
                if (q == 0) ssm[pass][rl][wid] = ss;
                __syncthreads();                   // all warps' partials in
                const float4 sp = *(const float4*)&ssm[pass][rl][0];
                const float inv = rsqrtf(sp.x + sp.y + sp.z + sp.w);

                const size_t gr = (size_t)(ctaRow0 + t * TILE_R + row) * 32;
                y[gr + pD] = make_float4(d0 * inv, d1 * inv, d2 * inv, d3 * inv);
                y[gr + pG] = make_float4(g0 * inv, g1 * inv, g2 * inv, g3 * inv);
            }
            stage  = (stage  == STAGES - 1) ? 0 : stage + 1;
            pstage = (pstage == STAGES - 1) ? 0 : pstage + 1;
        }
    } else {
        // ───── Lowrank blocks 2 (k=0) and 5 (k=1), factored ─────
        // vc[a][d] = V[k][d][q]; u4[a][o] = U[k][4q+o][0..3]
        float vc[2][16];
        float4 u4[2][4];
        #pragma unroll
        for (int a = 0; a < 2; ++a) {
            #pragma unroll
            for (int d = 0; d < 16; ++d) vc[a][d] = V[a * 64 + d * 4 + q];
            #pragma unroll
            for (int o = 0; o < 4; ++o)
                u4[a][o] = *(const float4*)&U[a * 64 + (4 * q + o) * 4];
        }
        const int lbq = lane & 28;                // quad base lane

        int stage = 0, pstage = STAGES - 1;
        #pragma unroll 1
        for (int t = 0; t < NT; ++t) {
            const int tp = t + STAGES - 1;
            if (tp < NT) {
                const uint32_t dst0 = sbase + (uint32_t)(pstage * TILE_R * 512);
                const float4* src0 = gsrc0 + tp * TILE_R * 32;
                #pragma unroll
                for (int i = 0; i < 4; ++i)
                    cpa16(dst0 + (tid + 128 * i) * 16u, src0 + tid + 128 * i);
            }
            cpa_commit();
            cpa_wait3();
            __syncthreads();

            const float4* tile = &sx[stage][0];
            #pragma unroll
            for (int pass = 0; pass < 2; ++pass) {
                const int row = pass * 8 + rl;
                const float4* rowp = tile + row * 32;

                float4 lout[2];
                #pragma unroll
                for (int a = 0; a < 2; ++a) {
                    const int jb4 = (2 + 3 * a) * 4;
                    // t_q = dot(V[:,q], x_block)
                    float tq = 0.f;
                    #pragma unroll
                    for (int sb = 0; sb < 4; ++sb) {
                        const float4 xa = rowp[jb4 + sb];
                        tq = fmaf(xa.x, vc[a][4 * sb + 0], tq);
                        tq = fmaf(xa.y, vc[a][4 * sb + 1], tq);
                        tq = fmaf(xa.z, vc[a][4 * sb + 2], tq);
                        tq = fmaf(xa.w, vc[a][4 * sb + 3], tq);
                    }
                    const float t0 = __shfl_sync(0xffffffffu, tq, lbq + 0);
                    const float t1 = __shfl_sync(0xffffffffu, tq, lbq + 1);
                    const float t2 = __shfl_sync(0xffffffffu, tq, lbq + 2);
                    const float t3 = __shfl_sync(0xffffffffu, tq, lbq + 3);
                    float o0 = t0 * u4[a][0].x, o1 = t0 * u4[a][1].x;
                    float o2 = t0 * u4[a][2].x, o3 = t0 * u4[a][3].x;
                    o0 = fmaf(t1, u4[a][0].y, o0); o1 = fmaf(t1, u4[a][1].y, o1);
                    o2 = fmaf(t1, u4[a][2].y, o2); o3 = fmaf(t1, u4[a][3].y, o3);
                    o0 = fmaf(t2, u4[a][0].z, o0); o1 = fmaf(t2, u4[a][1].z, o1);
                    o2 = fmaf(t2, u4[a][2].z, o2); o3 = fmaf(t2, u4[a][3].z, o3);
                    o0 = fmaf(t3, u4[a][0].w, o0); o1 = fmaf(t3, u4[a][1].w, o1);
                    o2 = fmaf(t3, u4[a][2].w, o2); o3 = fmaf(t3, u4[a][3].w, o3);
                    lout[a] = make_float4(o0, o1, o2, o3);
                }

                float ss = lout[0].x * lout[0].x;
                ss = fmaf(lout[0].y, lout[0].y, ss);
                ss = fmaf(lout[0].z, lout[0].z, ss);
                ss = fmaf(lout[0].w, lout[0].w, ss);
                ss = fmaf(lout[1].x, lout[1].x, ss);
                ss = fmaf(lout[1].y, lout[1].y, ss);
                ss = fmaf(lout[1].z, lout[1].z, ss);
                ss = fmaf(lout[1].w, lout[1].w, ss);
                ss += __shfl_xor_sync(0xffffffffu, ss, 1);
                ss += __shfl_xor_sync(0xffffffffu, ss, 2);
                if (q == 0) ssm[pass][rl][3] = ss;
                __syncthreads();
                const float4 sp = *(const float4*)&ssm[pass][rl][0];
                const float inv = rsqrtf(sp.x + sp.y + sp.z + sp.w);

                const size_t gr = (size_t)(ctaRow0 + t * TILE_R + row) * 32;
                y[gr + 8 + q]  = make_float4(lout[0].x * inv, lout[0].y * inv,
                                             lout[0].z * inv, lout[0].w * inv);
                y[gr + 20 + q] = make_float4(lout[1].x * inv, lout[1].y * inv,
                                             lout[1].z * inv, lout[1].w * inv);
            }
            stage  = (stage  == STAGES - 1) ? 0 : stage + 1;
            pstage = (pstage == STAGES - 1) ? 0 : pstage + 1;
        }
    }
}

extern "C" void kernel_launch(void* const* d_in, const int* in_sizes, int n_in,
                              void* d_out, int out_size) {
    const float* x = (const float*)d_in[0];
    const float* W = (const float*)d_in[1];
    const float* s = (const float*)d_in[2];
    const float* U = (const float*)d_in[3];
    const float* V = (const float*)d_in[4];
    float* out = (float*)d_out;

    bdla_main<<<NCTA, 128>>>((const float4*)x, (float4*)out, W, s, U, V);
}

// round 17
// speedup vs baseline: 1.2259x; 1.2259x over previous
#include <cuda_runtime.h>
#include <math.h>
#include <stdint.h>

#define NROWS   262144
#define NCTA    2048
#define TILE_R  32                      // rows per pipeline stage (16 KB)
#define STAGES  2
#define NT      4                       // tiles per CTA (128 rows)

__device__ __forceinline__ void cpa16(uint32_t dst, const float4* src) {
    asm volatile("cp.async.cg.shared.global [%0], [%1], 16;"
                 :: "r"(dst), "l"(src));
}
__device__ __forceinline__ void cpa_commit() {
    asm volatile("cp.async.commit_group;");
}
__device__ __forceinline__ void cpa_wait1() {
    asm volatile("cp.async.wait_group 1;");
}

__global__ void __launch_bounds__(128, 5)
bdla_main(const float4* __restrict__ x, float4* __restrict__ y,
          const float* __restrict__ Wd, const float* __restrict__ s,
          const float* __restrict__ U, const float* __restrict__ V) {
    __shared__ float4 sx[STAGES][TILE_R * 32];   // 2 x 16 KB
    __shared__ float  swt[2048];                 // swt[j*256 + d*16 + ob]

    const int tid  = threadIdx.x;
    const int lane = tid & 31;
    const int wid  = tid >> 5;                   // 0..3
    const int j    = lane >> 2;                  // block id
    const int q    = lane & 3;                   // output quad
    const unsigned ctaRow0 = blockIdx.x * (TILE_R * NT);

    const float4* gsrc0 = x + (size_t)ctaRow0 * 32;
    const uint32_t sbase = (uint32_t)__cvta_generic_to_shared(&sx[0][0]);

    // Prologue: prefetch tile 0 (one commit group). 32 rows = 1024 float4;
    // 128 threads x 8 cp.async each.
    {
        const float4* src0 = gsrc0;
        #pragma unroll
        for (int i = 0; i < 8; ++i)
            cpa16(sbase + (tid + 128 * i) * 16u, src0 + tid + 128 * i);
        cpa_commit();
    }

    // Build unified per-block 16x16 matrices in smem, fully unrolled so all
    // parameter LDGs overlap (R13-proven). DENSE {0,3,6}: M[d][ob]=W[k][ob][d];
    // DIAG {1,4,7}: diag(s); LR {2,5}: (V U^T)[d][ob].
    #pragma unroll
    for (int i = 0; i < 16; ++i) {
        const int e = tid + 128 * i;
        const int jj = e >> 8;
        const int rem = e & 255;
        const int d = rem >> 4;
        const int o = rem & 15;
        float val;
        if (jj == 0 || jj == 3 || jj == 6) {
            const int k = jj / 3;
            val = Wd[k * 256 + o * 16 + d];
        } else if (jj == 1 || jj == 4 || jj == 7) {
            const int k = (jj - 1) / 3;
            val = (d == o) ? s[k * 16 + d] : 0.0f;
        } else {
            const int k = (jj - 2) / 3;
            float acc = 0.0f;
            #pragma unroll
            for (int r = 0; r < 4; ++r)
                acc += V[k * 64 + d * 4 + r] * U[k * 64 + o * 4 + r];
            val = acc;
        }
        swt[e] = val;
    }
    __syncthreads();

    // 64 weight registers per lane: w[d] = M[j][d][4q..4q+3].
    float4 w[16];
    {
        const float4* Mp = (const float4*)&swt[j * 256 + q * 4];
        #pragma unroll
        for (int d = 0; d < 16; ++d) w[d] = Mp[d * 4];
    }
    // swt read-only from here on.

    int stage = 0;
    #pragma unroll 1
    for (int t = 0; t < NT; ++t) {
        // Issue tile t+1 into the other stage; empty commit groups keep the
        // wait_group count aligned past the end.
        const int tp = t + 1;
        if (tp < NT) {
            const uint32_t dst0 = sbase + (uint32_t)((stage ^ 1) * TILE_R * 512);
            const float4* src0 = gsrc0 + tp * TILE_R * 32;
            #pragma unroll
            for (int i = 0; i < 8; ++i)
                cpa16(dst0 + (tid + 128 * i) * 16u, src0 + tid + 128 * i);
        }
        cpa_commit();

        cpa_wait1();              // tile t's group complete (<=1 pending)
        __syncthreads();          // visible to all warps

        const float4* tile = &sx[stage][0];

        // Two 16-row halves, each identical to the R13 body (register shape
        // preserved); 8 rows per warp total.
        #pragma unroll
        for (int half = 0; half < 2; ++half) {
            #pragma unroll
            for (int k = 0; k < 4; ++k) {
                const int rit = 16 * half + wid + 4 * k;
                const float4* rowp = tile + rit * 32 + j * 4;

                float y0 = 0.f, y1 = 0.f, y2 = 0.f, y3 = 0.f;
                #pragma unroll
                for (int sb = 0; sb < 4; ++sb) {
                    const float4 a = rowp[sb];       // quad-broadcast LDS.128
                    const float4 w0 = w[4 * sb + 0];
                    const float4 w1 = w[4 * sb + 1];
                    const float4 w2 = w[4 * sb + 2];
                    const float4 w3 = w[4 * sb + 3];
                    y0 = fmaf(a.x, w0.x, y0); y1 = fmaf(a.x, w0.y, y1);
                    y2 = fmaf(a.x, w0.z, y2); y3 = fmaf(a.x, w0.w, y3);
                    y0 = fmaf(a.y, w1.x, y0); y1 = fmaf(a.y, w1.y, y1);
                    y2 = fmaf(a.y, w1.z, y2); y3 = fmaf(a.y, w1.w, y3);
                    y0 = fmaf(a.z, w2.x, y0); y1 = fmaf(a.z, w2.y, y1);
                    y2 = fmaf(a.z, w2.z, y2); y3 = fmaf(a.z, w2.w, y3);
                    y0 = fmaf(a.w, w3.x, y0); y1 = fmaf(a.w, w3.y, y1);
                    y2 = fmaf(a.w, w3.z, y2); y3 = fmaf(a.w, w3.w, y3);
                }

                // Row L2 norm across all 32 lanes.
                float ss = y0 * y0;
                ss = fmaf(y1, y1, ss); ss = fmaf(y2, y2, ss);
                ss = fmaf(y3, y3, ss);
                #pragma unroll
                for (int m = 16; m >= 1; m >>= 1)
                    ss += __shfl_xor_sync(0xffffffffu, ss, m);
                const float inv = rsqrtf(ss);

                const unsigned grow = ctaRow0 + (unsigned)(t * TILE_R + rit);
                y[(size_t)grow * 32 + lane] =
                    make_float4(y0 * inv, y1 * inv, y2 * inv, y3 * inv);
            }
        }

        __syncthreads();          // this stage is reused by the issue at t+1
        stage ^= 1;
    }
}

extern "C" void kernel_launch(void* const* d_in, const int* in_sizes, int n_in,
                              void* d_out, int out_size) {
    const float* x = (const float*)d_in[0];
    const float* W = (const float*)d_in[1];
    const float* s = (const float*)d_in[2];
    const float* U = (const float*)d_in[3];
    const float* V = (const float*)d_in[4];
    float* out = (float*)d_out;

    bdla_main<<<NCTA, 128>>>((const float4*)x, (float4*)out, W, s, U, V);
}